// round 1
// baseline (speedup 1.0000x reference)
#include <cuda_runtime.h>
#include <math.h>
#include <float.h>
#include <stdint.h>

// Problem constants
#define BB   2
#define NN   4096
#define KK   32      // KNN
#define KO_  32      // offset bins
#define HH   64
#define WW   64
#define K2_BLOCKS 2048

#define EPS      1e-6f
#define LAMBDA0  0.001f
#define TAU2X2   4.5f      // 2*1.5^2 (+1e-12 negligible)
#define ETA      8.0f
#define ALPHA    10.0f
#define BETA     8.0f
#define BETAP    8.0f

// ---------------- scratch (static device globals; no runtime alloc) ----------
__device__ float g_kappa[(size_t)BB*NN*KK*KO_];   // 33.5 MB
__device__ float g_vals [BB*NN*KK];
__device__ int   g_idx  [BB*NN*KK];
__device__ float g_a1e  [BB*NN*KK];
__device__ float g_chi  [BB*NN*KK];
__device__ float g_a2e  [BB*NN*KK];
__device__ float g_m    [BB*NN];
__device__ float g_q    [BB*NN];
__device__ float g_sev  [BB*NN];
__device__ float g_tev  [BB*NN];
__device__ float g_hpart[K2_BLOCKS*2*32];
__device__ float g_wsoft[BB*32];
__device__ float g_wmean[32];

__device__ __forceinline__ float warp_sum(float x){
    #pragma unroll
    for(int o=16;o;o>>=1) x += __shfl_xor_sync(0xffffffffu,x,o);
    return x;
}
__device__ __forceinline__ float warp_max(float x){
    #pragma unroll
    for(int o=16;o;o>>=1) x = fmaxf(x,__shfl_xor_sync(0xffffffffu,x,o));
    return x;
}

// ---------------- K1: per-row top-32 of A0 (sorted desc, min-index ties) -----
__global__ void k_topk(const float* __restrict__ A0){
    __shared__ float s[NN];
    __shared__ float topv[KK];
    __shared__ int   topi[KK];
    __shared__ float wv[8];
    __shared__ int   wi[8];
    const int row = blockIdx.x;               // b*NN + i
    const int tid = threadIdx.x;
    const float4* a4 = (const float4*)(A0 + (size_t)row*NN);
    for(int t=tid; t<NN/4; t+=256) ((float4*)s)[t] = a4[t];
    __syncthreads();

    const int warp = tid>>5, lane = tid&31;
    const int base = warp*512;
    for(int it=0; it<KK; ++it){
        float bv = -FLT_MAX; int bi = 0x7fffffff;
        #pragma unroll
        for(int t=0;t<16;t++){
            int j = base + t*32 + lane;
            float v = s[j];
            if(v>bv || (v==bv && j<bi)){ bv=v; bi=j; }
        }
        #pragma unroll
        for(int off=16;off;off>>=1){
            float ov = __shfl_down_sync(0xffffffffu,bv,off);
            int   oi = __shfl_down_sync(0xffffffffu,bi,off);
            if(ov>bv || (ov==bv && oi<bi)){ bv=ov; bi=oi; }
        }
        if(lane==0){ wv[warp]=bv; wi[warp]=bi; }
        __syncthreads();
        if(tid==0){
            float mv=wv[0]; int mi=wi[0];
            #pragma unroll
            for(int w=1;w<8;w++){
                if(wv[w]>mv || (wv[w]==mv && wi[w]<mi)){ mv=wv[w]; mi=wi[w]; }
            }
            topv[it]=mv; topi[it]=mi; s[mi]=-FLT_MAX;
        }
        __syncthreads();
    }
    if(tid<KK){
        g_vals[(size_t)row*KK+tid]=topv[tid];
        g_idx [(size_t)row*KK+tid]=topi[tid];
    }
}

// ---------------- K2: kappa per edge + deterministic Hbins partials ----------
// warp-per-edge, lane = bin o
__global__ void k_kappa(const float* __restrict__ P, const float* __restrict__ bins){
    const int lane = threadIdx.x & 31;
    const int wloc = threadIdx.x >> 5;
    const int warpg = blockIdx.x*8 + wloc;
    const int nwarps = K2_BLOCKS*8;
    const float bx = bins[lane*2+0];
    const float by = bins[lane*2+1];
    float h0=0.f, h1=0.f;
    const int NE = BB*NN*KK;
    for(int e=warpg; e<NE; e+=nwarps){
        int row = e>>5;
        int i   = row & (NN-1);
        int j   = g_idx[e];
        float vx = P[j*2+0]-P[i*2+0];
        float vy = P[j*2+1]-P[i*2+1];
        float dx = vx-bx, dy = vy-by;
        float kap = expf(-(dx*dx+dy*dy)/TAU2X2);
        g_kappa[(size_t)e*KO_+lane] = kap;
        float c = g_vals[e]*kap;
        if(row < NN) h0 += c; else h1 += c;
    }
    __shared__ float sh[8][2][32];
    sh[wloc][0][lane]=h0; sh[wloc][1][lane]=h1;
    __syncthreads();
    if(wloc==0){
        float a0=0.f,a1=0.f;
        #pragma unroll
        for(int w=0;w<8;w++){ a0+=sh[w][0][lane]; a1+=sh[w][1][lane]; }
        g_hpart[(blockIdx.x*2+0)*32+lane]=a0;
        g_hpart[(blockIdx.x*2+1)*32+lane]=a1;
    }
}

// ---------------- K3: Hbins reduce -> Wsoft (softmax) + Wmean ----------------
__global__ void k_soft(){
    const int tid=threadIdx.x;           // 64 threads: warp0=b0, warp1=b1
    const int b=tid>>5, o=tid&31;
    float h=0.f;
    for(int blk=0; blk<K2_BLOCKS; ++blk) h += g_hpart[(blk*2+b)*32+o];
    float x = ETA*h;
    float mx = warp_max(x);
    float ex = expf(x-mx);
    float se = warp_sum(ex);
    float w  = ex/se;
    g_wsoft[b*32+o]=w;
    __shared__ float sh[2][32];
    sh[b][o]=w;
    __syncthreads();
    if(b==0) g_wmean[o]=0.5f*(sh[0][o]+sh[1][o]);
}

// ---------------- K4: per-row (warp): R, A1_edges, entropy->U, chi -----------
__global__ void k_row1(float* __restrict__ outU){
    const int warp = threadIdx.x>>5, lane = threadIdx.x&31;
    const int row  = blockIdx.x*8 + warp;
    const int b    = row >> 12;
    __shared__ float sk[8][32*33];
    float* s = sk[warp];
    const size_t kbase = (size_t)row*KK*KO_;
    #pragma unroll 4
    for(int t=0;t<32;t++) s[t*33+lane] = g_kappa[kbase + (size_t)t*32 + lane];
    __syncwarp();
    const float wl = g_wsoft[b*32+lane];
    const float wm = g_wmean[lane];
    float r = LAMBDA0, chi = 0.f;
    #pragma unroll
    for(int o=0;o<32;o++){
        float kv = s[lane*33+o];
        r   = fmaf(__shfl_sync(0xffffffffu, wl, o), kv, r);
        chi = fmaf(__shfl_sync(0xffffffffu, wm, o), kv, chi);
    }
    const float val = g_vals[(size_t)row*KK+lane];
    float ta = val*r;
    float S  = warp_sum(ta);
    float a1 = ta/(S+EPS);
    g_a1e[(size_t)row*KK+lane]=a1;
    g_chi[(size_t)row*KK+lane]=chi;
    // entropy of softmax(ALPHA*a1)
    float x  = ALPHA*a1;
    float mx = warp_max(x);
    float ex = expf(x-mx);
    float se = warp_sum(ex);
    float p  = ex/se;
    float t  = p*logf(p+EPS);
    float ent= -warp_sum(t);
    float U  = 1.f/(1.f+expf(ent));   // sigmoid(-ent)
    if(lane==0){ outU[row]=U; g_m[row]=1.f-U; }
}

// ---------------- K5: per-row (block): A2 edges, dense row write, q ----------
__global__ void k_row2(float* __restrict__ outA2){
    __shared__ float srow[NN];
    __shared__ float sfin[KK];
    __shared__ int   sidx[KK];
    const int row = blockIdx.x;
    const int b   = row >> 12;
    const int tid = threadIdx.x;
    float4 z = make_float4(0.f,0.f,0.f,0.f);
    for(int t=tid; t<NN/4; t+=256) ((float4*)srow)[t]=z;
    if(tid<32){
        const int lane=tid;
        int   j  = g_idx[(size_t)row*KK+lane];
        float a1 = g_a1e[(size_t)row*KK+lane];
        float mi = g_m[row];
        float mj = g_m[(b<<12)+j];
        float hat= mi*a1*mj;
        float hs = warp_sum(hat);
        float a2 = hat/(hs+EPS);
        float rs = warp_sum(a2);
        float fin= a2/(rs+EPS);
        g_a2e[(size_t)row*KK+lane]=fin;
        sidx[lane]=j; sfin[lane]=fin;
        // w_local = softmax(BETAP*a2); q = sum(w_local*chi)
        float x  = BETAP*a2;
        float mx = warp_max(x);
        float ex = expf(x-mx);
        float se = warp_sum(ex);
        float wlc= ex/se;
        float q  = warp_sum(wlc*g_chi[(size_t)row*KK+lane]);
        if(lane==0) g_q[row]=q;
    }
    __syncthreads();
    if(tid<32) srow[sidx[tid]] = sfin[tid];
    __syncthreads();
    float4* o4 = (float4*)(outA2 + (size_t)row*NN);
    for(int t=tid; t<NN/4; t+=256) o4[t]=((float4*)srow)[t];
}

// ---------------- K6: directional evidence over sparse edges -----------------
__global__ void k_zero_st(){
    int t = blockIdx.x*blockDim.x+threadIdx.x;
    if(t < BB*NN){ g_sev[t]=0.f; g_tev[t]=0.f; }
}
__global__ void k_dir(const float* __restrict__ A2){
    int e = blockIdx.x*blockDim.x+threadIdx.x;
    if(e >= BB*NN*KK) return;
    int row = e>>5;
    int b   = row>>12;
    int r   = row&(NN-1);
    int c   = g_idx[e];
    float val = g_a2e[e];
    float rev = A2[((size_t)(b<<12)+c)*NN + r];
    float pd;
    if(r==c) pd = 0.f;
    else{
        float ef = expf(BETA*val);
        float er = expf(BETA*rev);
        pd = ef/(ef+er+EPS);
    }
    atomicAdd(&g_sev[row],      val*pd);
    atomicAdd(&g_tev[(b<<12)+c], val*(1.f-pd));
}

// ---------------- K7: pi_src / pi_tgt ----------------------------------------
__global__ void k_pi(float* __restrict__ outS, float* __restrict__ outT){
    int t = blockIdx.x*blockDim.x+threadIdx.x;
    if(t < BB*NN){
        float s=g_sev[t], tt=g_tev[t];
        float ps = s/(s+tt+EPS);
        outS[t]=ps; outT[t]=1.f-ps;
    }
}

// ---------------- K8: 5x5 gaussian conv + sigmoid ----------------------------
__global__ void k_conv(const float* __restrict__ gk, float* __restrict__ outM){
    int t = blockIdx.x*blockDim.x+threadIdx.x;
    if(t >= BB*NN) return;
    int b = t>>12; int yx = t&(NN-1);
    int y = yx>>6, x = yx&63;
    const float* q = g_q + (b<<12);
    float acc = 0.f;
    #pragma unroll
    for(int dy=0;dy<5;dy++){
        int yy=y+dy-2;
        if(yy<0||yy>=HH) continue;
        #pragma unroll
        for(int dx=0;dx<5;dx++){
            int xx=x+dx-2;
            if(xx<0||xx>=WW) continue;
            acc = fmaf(q[yy*WW+xx], gk[dy*5+dx], acc);
        }
    }
    outM[t] = 1.f/(1.f+expf(-acc));
}

// ---------------- launch ------------------------------------------------------
extern "C" void kernel_launch(void* const* d_in, const int* in_sizes, int n_in,
                              void* d_out, int out_size){
    // inputs: 0=E (unused), 1=A0, 2=P, 3=bins, 4=smooth_kernel
    const float* A0   = (const float*)d_in[1];
    const float* P    = (const float*)d_in[2];
    const float* bins = (const float*)d_in[3];
    const float* sker = (const float*)d_in[4];
    float* out = (float*)d_out;

    const size_t OFF_A2  = 0;
    const size_t OFF_U   = (size_t)BB*NN*NN;
    const size_t OFF_PS  = OFF_U  + BB*NN;
    const size_t OFF_PT  = OFF_PS + BB*NN;
    const size_t OFF_MAP = OFF_PT + BB*NN;

    k_topk <<<BB*NN, 256>>>(A0);
    k_kappa<<<K2_BLOCKS, 256>>>(P, bins);
    k_soft <<<1, 64>>>();
    k_row1 <<<BB*NN/8, 256>>>(out + OFF_U);
    k_row2 <<<BB*NN, 256>>>(out + OFF_A2);
    k_zero_st<<<(BB*NN+255)/256, 256>>>();
    k_dir  <<<(BB*NN*KK+255)/256, 256>>>(out + OFF_A2);
    k_pi   <<<(BB*NN+255)/256, 256>>>(out + OFF_PS, out + OFF_PT);
    k_conv <<<(BB*NN+255)/256, 256>>>(sker, out + OFF_MAP);
}

// round 2
// speedup vs baseline: 2.5257x; 2.5257x over previous
#include <cuda_runtime.h>
#include <math.h>
#include <float.h>
#include <stdint.h>

#define BB   2
#define NN   4096
#define KK   32
#define HH   64
#define WW   64
#define NOFF 127
#define NOFF2 (127*127)

#define EPS      1e-6f
#define LAMBDA0  0.001f
#define TAU2X2   4.5f
#define ETA      8.0f
#define ALPHA    10.0f
#define BETA     8.0f
#define BETAP    8.0f

#define T0   0.98f
#define CAP  1536
#define HB   256      // hist blocks

// ---------------- static device scratch --------------------------------------
__device__ float g_kt  [(size_t)NOFF2*32];     // kappa table, 2 MB
__device__ float g_vals[BB*NN*KK];
__device__ int   g_idx [BB*NN*KK];
__device__ int   g_off [BB*NN*KK];
__device__ float g_a1e [BB*NN*KK];
__device__ float g_chi [BB*NN*KK];
__device__ float g_a2e [BB*NN*KK];
__device__ float g_m   [BB*NN];
__device__ float g_q   [BB*NN];
__device__ float g_sev [BB*NN];
__device__ float g_tev [BB*NN];
__device__ float g_hpart[HB*2*32];
__device__ float g_wsoft[BB*32];
__device__ float g_wmean[32];

__device__ __forceinline__ float warp_sum(float x){
    #pragma unroll
    for(int o=16;o;o>>=1) x += __shfl_xor_sync(0xffffffffu,x,o);
    return x;
}
__device__ __forceinline__ float warp_max(float x){
    #pragma unroll
    for(int o=16;o;o>>=1) x = fmaxf(x,__shfl_xor_sync(0xffffffffu,x,o));
    return x;
}

// ---------------- K0: kappa table (+ zero g_tev) ------------------------------
__global__ void k_table(const float* __restrict__ bins){
    const int lane = threadIdx.x & 31;
    const int wloc = threadIdx.x >> 5;
    const int off  = blockIdx.x*8 + wloc;
    if(off < NOFF2){
        float vx = (float)(off % NOFF - 63);
        float vy = (float)(off / NOFF - 63);
        float dx = vx - bins[lane*2+0];
        float dy = vy - bins[lane*2+1];
        g_kt[(size_t)off*32 + lane] = expf(-(dx*dx+dy*dy)/TAU2X2);
    }
    int t = blockIdx.x*blockDim.x + threadIdx.x;
    if(t < BB*NN) g_tev[t] = 0.f;
}

// ---------------- K1: top-32 per row (threshold + exact select) ---------------
__global__ void k_topk(const float* __restrict__ A0){
    __shared__ float cv[CAP];
    __shared__ int   ci[CAP];
    __shared__ int   cnt;
    __shared__ float topv[KK];
    __shared__ int   topi[KK];
    __shared__ float srow[NN];           // fallback only
    __shared__ float wvs[8];
    __shared__ int   wis[8];

    const int row = blockIdx.x;
    const int tid = threadIdx.x;
    const float4* a4 = (const float4*)(A0 + (size_t)row*NN);
    if(tid==0) cnt = 0;
    __syncthreads();

    #pragma unroll
    for(int k=0;k<4;k++){
        float4 f = a4[k*256 + tid];
        float mm = fmaxf(fmaxf(f.x,f.y), fmaxf(f.z,f.w));
        if(mm > T0){
            int jb = (k*256 + tid)*4;
            if(f.x>T0){ int p=atomicAdd(&cnt,1); if(p<CAP){cv[p]=f.x; ci[p]=jb+0;} }
            if(f.y>T0){ int p=atomicAdd(&cnt,1); if(p<CAP){cv[p]=f.y; ci[p]=jb+1;} }
            if(f.z>T0){ int p=atomicAdd(&cnt,1); if(p<CAP){cv[p]=f.z; ci[p]=jb+2;} }
            if(f.w>T0){ int p=atomicAdd(&cnt,1); if(p<CAP){cv[p]=f.w; ci[p]=jb+3;} }
        }
    }
    __syncthreads();
    const int C = cnt;

    if(C >= KK && C <= CAP){
        // exact top-32 from C candidates, one warp
        if(tid < 32){
            const int lane = tid;
            for(int it=0; it<KK; ++it){
                float bv = -FLT_MAX; int bi = 0x7fffffff;
                for(int t=lane; t<C; t+=32){
                    float v = cv[t]; int j = ci[t];
                    if(v>bv || (v==bv && j<bi)){ bv=v; bi=j; }
                }
                #pragma unroll
                for(int o=16;o;o>>=1){
                    float ov = __shfl_down_sync(0xffffffffu,bv,o);
                    int   oi = __shfl_down_sync(0xffffffffu,bi,o);
                    if(ov>bv || (ov==bv && oi<bi)){ bv=ov; bi=oi; }
                }
                bv = __shfl_sync(0xffffffffu,bv,0);
                bi = __shfl_sync(0xffffffffu,bi,0);
                if(lane==0){ topv[it]=bv; topi[it]=bi; }
                for(int t=lane; t<C; t+=32) if(ci[t]==bi) cv[t] = -FLT_MAX;
                __syncwarp();
            }
        }
    } else {
        // deterministic fallback: stage row, 32 iterative block-argmax rounds
        for(int t=tid; t<NN/4; t+=256) ((float4*)srow)[t] = a4[t];
        __syncthreads();
        const int warp = tid>>5, lane = tid&31, base = warp*512;
        for(int it=0; it<KK; ++it){
            float bv=-FLT_MAX; int bi=0x7fffffff;
            #pragma unroll
            for(int t=0;t<16;t++){
                int j = base + t*32 + lane;
                float v = srow[j];
                if(v>bv || (v==bv && j<bi)){ bv=v; bi=j; }
            }
            #pragma unroll
            for(int o=16;o;o>>=1){
                float ov = __shfl_down_sync(0xffffffffu,bv,o);
                int   oi = __shfl_down_sync(0xffffffffu,bi,o);
                if(ov>bv || (ov==bv && oi<bi)){ bv=ov; bi=oi; }
            }
            if(lane==0){ wvs[warp]=bv; wis[warp]=bi; }
            __syncthreads();
            if(tid==0){
                float mv=wvs[0]; int mi=wis[0];
                #pragma unroll
                for(int w=1;w<8;w++)
                    if(wvs[w]>mv || (wvs[w]==mv && wis[w]<mi)){ mv=wvs[w]; mi=wis[w]; }
                topv[it]=mv; topi[it]=mi; srow[mi]=-FLT_MAX;
            }
            __syncthreads();
        }
    }
    __syncthreads();

    if(tid < KK){
        const size_t e = (size_t)row*KK + tid;
        float v = topv[tid];
        int   j = topi[tid];
        g_vals[e] = v;
        g_idx [e] = j;
        int i  = row & (NN-1);
        int vx = (j&63) - (i&63);
        int vy = (j>>6) - (i>>6);
        g_off[e] = (vy+63)*NOFF + (vx+63);
    }
}

// ---------------- K2: Hbins partials (deterministic 2-level) ------------------
__global__ void k_hist(){
    const int lane = threadIdx.x & 31;
    const int wloc = threadIdx.x >> 5;
    const int w    = blockIdx.x*8 + wloc;      // 2048 warps
    float h0=0.f, h1=0.f;
    const int base = w*128;
    #pragma unroll
    for(int ch=0; ch<4; ch++){
        int e   = base + ch*32 + lane;
        int off = g_off[e];
        float val = g_vals[e];
        bool b0 = (base + ch*32) < NN*KK;       // uniform per chunk
        #pragma unroll
        for(int t=0;t<32;t++){
            int   ot = __shfl_sync(0xffffffffu, off, t);
            float vt = __shfl_sync(0xffffffffu, val, t);
            float kv = g_kt[(size_t)ot*32 + lane];
            if(b0) h0 = fmaf(vt, kv, h0); else h1 = fmaf(vt, kv, h1);
        }
    }
    __shared__ float sh[8][2][32];
    sh[wloc][0][lane]=h0; sh[wloc][1][lane]=h1;
    __syncthreads();
    if(wloc==0){
        float a0=0.f,a1=0.f;
        #pragma unroll
        for(int w2=0;w2<8;w2++){ a0+=sh[w2][0][lane]; a1+=sh[w2][1][lane]; }
        g_hpart[(blockIdx.x*2+0)*32+lane]=a0;
        g_hpart[(blockIdx.x*2+1)*32+lane]=a1;
    }
}

// ---------------- K3: Hbins reduce -> Wsoft + Wmean ---------------------------
__global__ void k_soft(){
    const int tid=threadIdx.x;                 // 64 threads
    const int b=tid>>5, o=tid&31;
    float h=0.f;
    for(int blk=0; blk<HB; ++blk) h += g_hpart[(blk*2+b)*32+o];
    float x  = ETA*h;
    float mx = warp_max(x);
    float ex = expf(x-mx);
    float se = warp_sum(ex);
    float wv = ex/se;
    g_wsoft[b*32+o]=wv;
    __shared__ float sh[2][32];
    sh[b][o]=wv;
    __syncthreads();
    if(b==0) g_wmean[o]=0.5f*(sh[0][o]+sh[1][o]);
}

// ---------------- K4: per-row warp: R, A1_edges, entropy->U, chi --------------
__global__ void k_row1(float* __restrict__ outU){
    const int warp = threadIdx.x>>5, lane = threadIdx.x&31;
    const int row  = blockIdx.x*8 + warp;
    const int b    = row >> 12;
    const size_t e = (size_t)row*KK + lane;
    const int off  = g_off[e];
    const float* krow = g_kt + (size_t)off*32;
    float kv[32];
    #pragma unroll
    for(int t=0;t<8;t++){
        float4 f = ((const float4*)krow)[t];
        kv[4*t+0]=f.x; kv[4*t+1]=f.y; kv[4*t+2]=f.z; kv[4*t+3]=f.w;
    }
    const float wl = g_wsoft[b*32+lane];
    const float wm = g_wmean[lane];
    float r = LAMBDA0, chi = 0.f;
    #pragma unroll
    for(int o=0;o<32;o++){
        r   = fmaf(__shfl_sync(0xffffffffu, wl, o), kv[o], r);
        chi = fmaf(__shfl_sync(0xffffffffu, wm, o), kv[o], chi);
    }
    const float val = g_vals[e];
    float ta = val*r;
    float S  = warp_sum(ta);
    float a1 = ta/(S+EPS);
    g_a1e[e]=a1;
    g_chi[e]=chi;
    float x  = ALPHA*a1;
    float mx = warp_max(x);
    float ex = expf(x-mx);
    float se = warp_sum(ex);
    float p  = ex/se;
    float t  = p*logf(p+EPS);
    float ent= -warp_sum(t);
    float U  = 1.f/(1.f+expf(ent));
    if(lane==0){ outU[row]=U; g_m[row]=1.f-U; }
}

// ---------------- K5: per-row block: A2 edges, dense write, q -----------------
__global__ void k_row2(float* __restrict__ outA2){
    __shared__ float srow[NN];
    __shared__ float sfin[KK];
    __shared__ int   sidx[KK];
    const int row = blockIdx.x;
    const int b   = row >> 12;
    const int tid = threadIdx.x;
    float4 z = make_float4(0.f,0.f,0.f,0.f);
    for(int t=tid; t<NN/4; t+=256) ((float4*)srow)[t]=z;
    if(tid<32){
        const int lane=tid;
        const size_t e = (size_t)row*KK + lane;
        int   j  = g_idx[e];
        float a1 = g_a1e[e];
        float mi = g_m[row];
        float mj = g_m[(b<<12)+j];
        float hat= mi*a1*mj;
        float hs = warp_sum(hat);
        float a2 = hat/(hs+EPS);
        float rs = warp_sum(a2);
        float fin= a2/(rs+EPS);
        g_a2e[e]=fin;
        sidx[lane]=j; sfin[lane]=fin;
        float x  = BETAP*a2;
        float mx = warp_max(x);
        float ex = expf(x-mx);
        float se = warp_sum(ex);
        float wlc= ex/se;
        float q  = warp_sum(wlc*g_chi[e]);
        if(lane==0) g_q[row]=q;
    }
    __syncthreads();
    if(tid<32) srow[sidx[tid]] = sfin[tid];
    __syncthreads();
    float4* o4 = (float4*)(outA2 + (size_t)row*NN);
    for(int t=tid; t<NN/4; t+=256) o4[t]=((float4*)srow)[t];
}

// ---------------- K6: directional evidence (warp per row) ---------------------
__global__ void k_dir(const float* __restrict__ A2){
    const int lane = threadIdx.x & 31;
    const int wloc = threadIdx.x >> 5;
    const int w    = blockIdx.x*8 + wloc;      // 2048 warps
    for(int row=w; row<BB*NN; row+=2048){
        const size_t e = (size_t)row*KK + lane;
        int b = row>>12, r = row&(NN-1);
        int c = g_idx[e];
        float val = g_a2e[e];
        float rev = A2[((size_t)(b<<12)+c)*NN + r];
        float pd = 0.f;
        if(r != c){
            float ef = __expf(BETA*val);
            float er = __expf(BETA*rev);
            pd = ef/(ef+er+EPS);
        }
        float s = warp_sum(val*pd);
        if(lane==0) g_sev[row]=s;
        atomicAdd(&g_tev[(b<<12)+c], val*(1.f-pd));
    }
}

// ---------------- K7: pi ------------------------------------------------------
__global__ void k_pi(float* __restrict__ outS, float* __restrict__ outT){
    int t = blockIdx.x*blockDim.x+threadIdx.x;
    if(t < BB*NN){
        float s=g_sev[t], tt=g_tev[t];
        float ps = s/(s+tt+EPS);
        outS[t]=ps; outT[t]=1.f-ps;
    }
}

// ---------------- K8: 5x5 gaussian conv + sigmoid -----------------------------
__global__ void k_conv(const float* __restrict__ gk, float* __restrict__ outM){
    int t = blockIdx.x*blockDim.x+threadIdx.x;
    if(t >= BB*NN) return;
    int b = t>>12; int yx = t&(NN-1);
    int y = yx>>6, x = yx&63;
    const float* q = g_q + (b<<12);
    float acc = 0.f;
    #pragma unroll
    for(int dy=0;dy<5;dy++){
        int yy=y+dy-2;
        if(yy<0||yy>=HH) continue;
        #pragma unroll
        for(int dx=0;dx<5;dx++){
            int xx=x+dx-2;
            if(xx<0||xx>=WW) continue;
            acc = fmaf(q[yy*WW+xx], gk[dy*5+dx], acc);
        }
    }
    outM[t] = 1.f/(1.f+expf(-acc));
}

// ---------------- launch ------------------------------------------------------
extern "C" void kernel_launch(void* const* d_in, const int* in_sizes, int n_in,
                              void* d_out, int out_size){
    // inputs: 0=E (unused), 1=A0, 2=P, 3=bins, 4=smooth_kernel
    const float* A0   = (const float*)d_in[1];
    const float* bins = (const float*)d_in[3];
    const float* sker = (const float*)d_in[4];
    float* out = (float*)d_out;

    const size_t OFF_A2  = 0;
    const size_t OFF_U   = (size_t)BB*NN*NN;
    const size_t OFF_PS  = OFF_U  + BB*NN;
    const size_t OFF_PT  = OFF_PS + BB*NN;
    const size_t OFF_MAP = OFF_PT + BB*NN;

    k_table<<<(NOFF2+7)/8, 256>>>(bins);
    k_topk <<<BB*NN, 256>>>(A0);
    k_hist <<<HB, 256>>>();
    k_soft <<<1, 64>>>();
    k_row1 <<<BB*NN/8, 256>>>(out + OFF_U);
    k_row2 <<<BB*NN, 256>>>(out + OFF_A2);
    k_dir  <<<HB, 256>>>(out + OFF_A2);
    k_pi   <<<(BB*NN+255)/256, 256>>>(out + OFF_PS, out + OFF_PT);
    k_conv <<<(BB*NN+255)/256, 256>>>(sker, out + OFF_MAP);
}

// round 5
// speedup vs baseline: 2.6937x; 1.0665x over previous
#include <cuda_runtime.h>
#include <math.h>
#include <float.h>
#include <stdint.h>

#define BB   2
#define NN   4096
#define KK   32
#define HH   64
#define WW   64
#define NOFF 127
#define NOFF2 (127*127)

#define EPS      1e-6f
#define LAMBDA0  0.001f
#define TAU2X2   4.5f
#define ETA      8.0f
#define ALPHA    10.0f
#define BETA     8.0f
#define BETAP    8.0f

#define T0   0.98f
#define CAP  512

// ---------------- static device scratch --------------------------------------
__device__ float g_kt  [(size_t)NOFF2*32];     // kappa table [off][bin], 2 MB
__device__ float g_ktT [(size_t)32*NOFF2];     // transposed  [bin][off], 2 MB
__device__ float g_w   [BB*NOFF2];             // per-offset value sums
__device__ float g_hbins[BB*32];
__device__ float g_vals[BB*NN*KK];
__device__ int   g_idx [BB*NN*KK];
__device__ int   g_off [BB*NN*KK];
__device__ float g_a1e [BB*NN*KK];
__device__ float g_chi [BB*NN*KK];
__device__ float g_a2e [BB*NN*KK];
__device__ float g_m   [BB*NN];
__device__ float g_q   [BB*NN];
__device__ float g_sev [BB*NN];
__device__ float g_tev [BB*NN];
__device__ float g_wsoft[BB*32];
__device__ float g_wmean[32];

__device__ __forceinline__ float warp_sum(float x){
    #pragma unroll
    for(int o=16;o;o>>=1) x += __shfl_xor_sync(0xffffffffu,x,o);
    return x;
}
__device__ __forceinline__ float warp_max(float x){
    #pragma unroll
    for(int o=16;o;o>>=1) x = fmaxf(x,__shfl_xor_sync(0xffffffffu,x,o));
    return x;
}

// ---------------- K0: kappa table + transpose + zero scratch ------------------
__global__ void k_table(const float* __restrict__ bins){
    const int lane = threadIdx.x & 31;
    const int wloc = threadIdx.x >> 5;
    const int off  = blockIdx.x*8 + wloc;
    if(off < NOFF2){
        float vx = (float)(off % NOFF - 63);
        float vy = (float)(off / NOFF - 63);
        float dx = vx - bins[lane*2+0];
        float dy = vy - bins[lane*2+1];
        float kv = expf(-(dx*dx+dy*dy)/TAU2X2);
        g_kt [(size_t)off*32 + lane] = kv;
        g_ktT[(size_t)lane*NOFF2 + off] = kv;
    }
    int t = blockIdx.x*blockDim.x + threadIdx.x;
    if(t < BB*NN) g_tev[t] = 0.f;
    if(t < BB*NOFF2) g_w[t] = 0.f;
}

// ---------------- K1: top-32 per row + fused w-scatter ------------------------
__global__ void k_topk(const float* __restrict__ A0){
    __shared__ float cv[CAP];
    __shared__ int   ci[CAP];
    __shared__ int   cnt;
    __shared__ float topv[KK];
    __shared__ int   topi[KK];
    __shared__ float srow[NN];           // fallback only
    __shared__ float wvs[8];
    __shared__ int   wis[8];

    const int row = blockIdx.x;
    const int tid = threadIdx.x;
    const float4* a4 = (const float4*)(A0 + (size_t)row*NN);
    if(tid==0) cnt = 0;
    __syncthreads();

    #pragma unroll
    for(int k=0;k<4;k++){
        float4 f = a4[k*256 + tid];
        float mm = fmaxf(fmaxf(f.x,f.y), fmaxf(f.z,f.w));
        if(mm > T0){
            int jb = (k*256 + tid)*4;
            if(f.x>T0){ int p=atomicAdd(&cnt,1); if(p<CAP){cv[p]=f.x; ci[p]=jb+0;} }
            if(f.y>T0){ int p=atomicAdd(&cnt,1); if(p<CAP){cv[p]=f.y; ci[p]=jb+1;} }
            if(f.z>T0){ int p=atomicAdd(&cnt,1); if(p<CAP){cv[p]=f.z; ci[p]=jb+2;} }
            if(f.w>T0){ int p=atomicAdd(&cnt,1); if(p<CAP){cv[p]=f.w; ci[p]=jb+3;} }
        }
    }
    __syncthreads();
    const int C = cnt;

    if(C >= KK && C <= CAP){
        if(tid < 32){
            const int lane = tid;
            for(int it=0; it<KK; ++it){
                float bv = -FLT_MAX; int bi = 0x7fffffff;
                for(int t=lane; t<C; t+=32){
                    float v = cv[t]; int j = ci[t];
                    if(v>bv || (v==bv && j<bi)){ bv=v; bi=j; }
                }
                #pragma unroll
                for(int o=16;o;o>>=1){
                    float ov = __shfl_down_sync(0xffffffffu,bv,o);
                    int   oi = __shfl_down_sync(0xffffffffu,bi,o);
                    if(ov>bv || (ov==bv && oi<bi)){ bv=ov; bi=oi; }
                }
                bv = __shfl_sync(0xffffffffu,bv,0);
                bi = __shfl_sync(0xffffffffu,bi,0);
                if(lane==0){ topv[it]=bv; topi[it]=bi; }
                for(int t=lane; t<C; t+=32) if(ci[t]==bi) cv[t] = -FLT_MAX;
                __syncwarp();
            }
        }
    } else {
        // deterministic fallback: stage row, 32 iterative block-argmax rounds
        for(int t=tid; t<NN/4; t+=256) ((float4*)srow)[t] = a4[t];
        __syncthreads();
        const int warp = tid>>5, lane = tid&31, base = warp*512;
        for(int it=0; it<KK; ++it){
            float bv=-FLT_MAX; int bi=0x7fffffff;
            #pragma unroll
            for(int t=0;t<16;t++){
                int j = base + t*32 + lane;
                float v = srow[j];
                if(v>bv || (v==bv && j<bi)){ bv=v; bi=j; }
            }
            #pragma unroll
            for(int o=16;o;o>>=1){
                float ov = __shfl_down_sync(0xffffffffu,bv,o);
                int   oi = __shfl_down_sync(0xffffffffu,bi,o);
                if(ov>bv || (ov==bv && oi<bi)){ bv=ov; bi=oi; }
            }
            if(lane==0){ wvs[warp]=bv; wis[warp]=bi; }
            __syncthreads();
            if(tid==0){
                float mv=wvs[0]; int mi=wis[0];
                #pragma unroll
                for(int w=1;w<8;w++)
                    if(wvs[w]>mv || (wvs[w]==mv && wis[w]<mi)){ mv=wvs[w]; mi=wis[w]; }
                topv[it]=mv; topi[it]=mi; srow[mi]=-FLT_MAX;
            }
            __syncthreads();
        }
    }
    __syncthreads();

    if(tid < KK){
        const size_t e = (size_t)row*KK + tid;
        float v = topv[tid];
        int   j = topi[tid];
        g_vals[e] = v;
        g_idx [e] = j;
        int i  = row & (NN-1);
        int vx = (j&63) - (i&63);
        int vy = (j>>6) - (i>>6);
        int off = (vy+63)*NOFF + (vx+63);
        g_off[e] = off;
        atomicAdd(&g_w[(row>>12)*NOFF2 + off], v);
    }
}

// ---------------- K2: Hbins matvec: H[b][o] = dot(w[b], ktT[o]) ---------------
__global__ void k_mat(){
    const int b = blockIdx.x >> 5;
    const int o = blockIdx.x & 31;
    const int tid = threadIdx.x;
    const float* wv = g_w   + (size_t)b*NOFF2;
    const float* kt = g_ktT + (size_t)o*NOFF2;
    float s = 0.f;
    for(int t=tid; t<NOFF2; t+=256) s = fmaf(wv[t], kt[t], s);
    __shared__ float sh[8];
    s = warp_sum(s);
    if((tid&31)==0) sh[tid>>5]=s;
    __syncthreads();
    if(tid<32){
        float v = (tid<8)? sh[tid] : 0.f;
        v = warp_sum(v);
        if(tid==0) g_hbins[blockIdx.x]=v;
    }
}

// ---------------- K3: softmax + Wmean ----------------------------------------
__global__ void k_soft(){
    const int tid=threadIdx.x;                 // 64 threads
    const int b=tid>>5, o=tid&31;
    float x  = ETA*g_hbins[b*32+o];
    float mx = warp_max(x);
    float ex = expf(x-mx);
    float se = warp_sum(ex);
    float wv = ex/se;
    g_wsoft[b*32+o]=wv;
    __shared__ float sh[2][32];
    sh[b][o]=wv;
    __syncthreads();
    if(b==0) g_wmean[o]=0.5f*(sh[0][o]+sh[1][o]);
}

// ---------------- K4: per-row warp: R, A1_edges, entropy->U, chi --------------
__global__ void k_row1(float* __restrict__ outU){
    const int warp = threadIdx.x>>5, lane = threadIdx.x&31;
    const int row  = blockIdx.x*8 + warp;
    const int b    = row >> 12;
    const size_t e = (size_t)row*KK + lane;
    const int off  = g_off[e];
    const float* krow = g_kt + (size_t)off*32;
    float kv[32];
    #pragma unroll
    for(int t=0;t<8;t++){
        float4 f = ((const float4*)krow)[t];
        kv[4*t+0]=f.x; kv[4*t+1]=f.y; kv[4*t+2]=f.z; kv[4*t+3]=f.w;
    }
    const float wl = g_wsoft[b*32+lane];
    const float wm = g_wmean[lane];
    float r = LAMBDA0, chi = 0.f;
    #pragma unroll
    for(int o=0;o<32;o++){
        r   = fmaf(__shfl_sync(0xffffffffu, wl, o), kv[o], r);
        chi = fmaf(__shfl_sync(0xffffffffu, wm, o), kv[o], chi);
    }
    const float val = g_vals[e];
    float ta = val*r;
    float S  = warp_sum(ta);
    float a1 = ta/(S+EPS);
    g_a1e[e]=a1;
    g_chi[e]=chi;
    float x  = ALPHA*a1;
    float mx = warp_max(x);
    float ex = expf(x-mx);
    float se = warp_sum(ex);
    float p  = ex/se;
    float t  = p*logf(p+EPS);
    float ent= -warp_sum(t);
    float U  = 1.f/(1.f+expf(ent));
    if(lane==0){ outU[row]=U; g_m[row]=1.f-U; }
}

// ---------------- K5: per-row block: A2 edges, dense write, q -----------------
__global__ void k_row2(float* __restrict__ outA2){
    __shared__ float srow[NN];
    __shared__ float sfin[KK];
    __shared__ int   sidx[KK];
    const int row = blockIdx.x;
    const int b   = row >> 12;
    const int tid = threadIdx.x;
    float4 z = make_float4(0.f,0.f,0.f,0.f);
    for(int t=tid; t<NN/4; t+=256) ((float4*)srow)[t]=z;
    if(tid<32){
        const int lane=tid;
        const size_t e = (size_t)row*KK + lane;
        int   j  = g_idx[e];
        float a1 = g_a1e[e];
        float mi = g_m[row];
        float mj = g_m[(b<<12)+j];
        float hat= mi*a1*mj;
        float hs = warp_sum(hat);
        float a2 = hat/(hs+EPS);
        float rs = warp_sum(a2);
        float fin= a2/(rs+EPS);
        g_a2e[e]=fin;
        sidx[lane]=j; sfin[lane]=fin;
        float x  = BETAP*a2;
        float mx = warp_max(x);
        float ex = __expf(x-mx);
        float se = warp_sum(ex);
        float wlc= ex/se;
        float q  = warp_sum(wlc*g_chi[e]);
        if(lane==0) g_q[row]=q;
    }
    __syncthreads();
    if(tid<32) srow[sidx[tid]] = sfin[tid];
    __syncthreads();
    float4* o4 = (float4*)(outA2 + (size_t)row*NN);
    for(int t=tid; t<NN/4; t+=256) o4[t]=((float4*)srow)[t];
}

// ---------------- K6: directional evidence (warp per row) ---------------------
__global__ void k_dir(const float* __restrict__ A2){
    const int lane = threadIdx.x & 31;
    const int wloc = threadIdx.x >> 5;
    const int w    = blockIdx.x*8 + wloc;      // 2048 warps
    for(int row=w; row<BB*NN; row+=2048){
        const size_t e = (size_t)row*KK + lane;
        int b = row>>12, r = row&(NN-1);
        int c = g_idx[e];
        float val = g_a2e[e];
        float rev = A2[((size_t)(b<<12)+c)*NN + r];
        float pd = 0.f;
        if(r != c){
            float ef = __expf(BETA*val);
            float er = __expf(BETA*rev);
            pd = ef/(ef+er+EPS);
        }
        float s = warp_sum(val*pd);
        if(lane==0) g_sev[row]=s;
        atomicAdd(&g_tev[(b<<12)+c], val*(1.f-pd));
    }
}

// ---------------- K7: pi + conv + sigmoid (fused) -----------------------------
__global__ void k_pi_conv(const float* __restrict__ gk,
                          float* __restrict__ outS, float* __restrict__ outT,
                          float* __restrict__ outM){
    int t = blockIdx.x*blockDim.x+threadIdx.x;
    if(t >= BB*NN) return;
    float s=g_sev[t], tt=g_tev[t];
    float ps = s/(s+tt+EPS);
    outS[t]=ps; outT[t]=1.f-ps;

    int b = t>>12; int yx = t&(NN-1);
    int y = yx>>6, x = yx&63;
    const float* q = g_q + (b<<12);
    float acc = 0.f;
    #pragma unroll
    for(int dy=0;dy<5;dy++){
        int yy=y+dy-2;
        if(yy<0||yy>=HH) continue;
        #pragma unroll
        for(int dx=0;dx<5;dx++){
            int xx=x+dx-2;
            if(xx<0||xx>=WW) continue;
            acc = fmaf(q[yy*WW+xx], gk[dy*5+dx], acc);
        }
    }
    outM[t] = 1.f/(1.f+expf(-acc));
}

// ---------------- launch ------------------------------------------------------
extern "C" void kernel_launch(void* const* d_in, const int* in_sizes, int n_in,
                              void* d_out, int out_size){
    // inputs: 0=E (unused), 1=A0, 2=P, 3=bins, 4=smooth_kernel
    const float* A0   = (const float*)d_in[1];
    const float* bins = (const float*)d_in[3];
    const float* sker = (const float*)d_in[4];
    float* out = (float*)d_out;

    const size_t OFF_A2  = 0;
    const size_t OFF_U   = (size_t)BB*NN*NN;
    const size_t OFF_PS  = OFF_U  + BB*NN;
    const size_t OFF_PT  = OFF_PS + BB*NN;
    const size_t OFF_MAP = OFF_PT + BB*NN;

    k_table<<<(NOFF2+7)/8, 256>>>(bins);
    k_topk <<<BB*NN, 256>>>(A0);
    k_mat  <<<64, 256>>>();
    k_soft <<<1, 64>>>();
    k_row1 <<<BB*NN/8, 256>>>(out + OFF_U);
    k_row2 <<<BB*NN, 256>>>(out + OFF_A2);
    k_dir  <<<256, 256>>>(out + OFF_A2);
    k_pi_conv<<<(BB*NN+255)/256, 256>>>(sker, out + OFF_PS, out + OFF_PT, out + OFF_MAP);
}

// round 6
// speedup vs baseline: 3.1972x; 1.1869x over previous
#include <cuda_runtime.h>
#include <math.h>
#include <float.h>
#include <stdint.h>

#define BB   2
#define NN   4096
#define KK   32
#define HH   64
#define WW   64
#define NOFF 127
#define NOFF2 (127*127)

#define EPS      1e-6f
#define LAMBDA0  0.001f
#define TAU2X2   4.5f
#define ETA      8.0f
#define ALPHA    10.0f
#define BETA     8.0f
#define BETAP    8.0f

#define T0   0.98f
#define CAP  512

// ---------------- static device scratch --------------------------------------
__device__ float g_kt  [(size_t)NOFF2*32];     // kappa table [off][bin], 2 MB
__device__ float g_ktT [(size_t)32*NOFF2];     // transposed  [bin][off], 2 MB
__device__ float g_w   [BB*NOFF2];             // per-offset value sums
__device__ float g_hbins[BB*32];
__device__ float g_vals[BB*NN*KK];
__device__ int   g_idx [BB*NN*KK];
__device__ int   g_off [BB*NN*KK];
__device__ float g_a1e [BB*NN*KK];
__device__ float g_chi [BB*NN*KK];
__device__ float g_a2e [BB*NN*KK];
__device__ float g_m   [BB*NN];
__device__ float g_q   [BB*NN];
__device__ float g_sev [BB*NN];
__device__ float g_tev [BB*NN];

__device__ __forceinline__ float warp_sum(float x){
    #pragma unroll
    for(int o=16;o;o>>=1) x += __shfl_xor_sync(0xffffffffu,x,o);
    return x;
}
__device__ __forceinline__ float warp_max(float x){
    #pragma unroll
    for(int o=16;o;o>>=1) x = fmaxf(x,__shfl_xor_sync(0xffffffffu,x,o));
    return x;
}

// ---------------- K0: kappa table + transpose + zero scratch ------------------
__global__ void k_table(const float* __restrict__ bins){
    const int lane = threadIdx.x & 31;
    const int wloc = threadIdx.x >> 5;
    const int off  = blockIdx.x*8 + wloc;
    if(off < NOFF2){
        float vx = (float)(off % NOFF - 63);
        float vy = (float)(off / NOFF - 63);
        float dx = vx - bins[lane*2+0];
        float dy = vy - bins[lane*2+1];
        float kv = __expf(-(dx*dx+dy*dy)/TAU2X2);
        g_kt [(size_t)off*32 + lane] = kv;
        g_ktT[(size_t)lane*NOFF2 + off] = kv;
    }
    int t = blockIdx.x*blockDim.x + threadIdx.x;
    if(t < BB*NN) g_tev[t] = 0.f;
    if(t < BB*NOFF2) g_w[t] = 0.f;
}

// ---------------- K1: top-32 per row (threshold + bitonic) + w-scatter --------
__global__ void k_topk(const float* __restrict__ A0){
    __shared__ float cv[CAP];
    __shared__ int   ci[CAP];
    __shared__ int   cnt;
    __shared__ float topv[KK];
    __shared__ int   topi[KK];
    __shared__ float srow[NN];           // fallback only
    __shared__ float wvs[8];
    __shared__ int   wis[8];

    const int row = blockIdx.x;
    const int tid = threadIdx.x;
    const float4* a4 = (const float4*)(A0 + (size_t)row*NN);
    if(tid==0) cnt = 0;
    __syncthreads();

    #pragma unroll
    for(int k=0;k<4;k++){
        float4 f = a4[k*256 + tid];
        float mm = fmaxf(fmaxf(f.x,f.y), fmaxf(f.z,f.w));
        if(mm > T0){
            int jb = (k*256 + tid)*4;
            if(f.x>T0){ int p=atomicAdd(&cnt,1); if(p<CAP){cv[p]=f.x; ci[p]=jb+0;} }
            if(f.y>T0){ int p=atomicAdd(&cnt,1); if(p<CAP){cv[p]=f.y; ci[p]=jb+1;} }
            if(f.z>T0){ int p=atomicAdd(&cnt,1); if(p<CAP){cv[p]=f.z; ci[p]=jb+2;} }
            if(f.w>T0){ int p=atomicAdd(&cnt,1); if(p<CAP){cv[p]=f.w; ci[p]=jb+3;} }
        }
    }
    __syncthreads();
    const int C = cnt;

    if(C >= KK && C <= 256){
        // pad to 256 and bitonic-sort (desc by val, asc by idx on ties)
        if(tid >= C && tid < 256){ cv[tid] = -FLT_MAX; ci[tid] = 0x7fffffff; }
        __syncthreads();
        #pragma unroll
        for(int k=2;k<=256;k<<=1){
            for(int j=k>>1;j>0;j>>=1){
                int ixj = tid ^ j;
                if(ixj > tid && tid < 256){
                    bool up = ((tid & k) == 0);
                    float va=cv[tid], vb=cv[ixj];
                    int   ia=ci[tid], ib=ci[ixj];
                    bool aFirst = (va>vb) || (va==vb && ia<ib);
                    if(up ? !aFirst : aFirst){
                        cv[tid]=vb; ci[tid]=ib; cv[ixj]=va; ci[ixj]=ia;
                    }
                }
                __syncthreads();
            }
        }
        if(tid<KK){ topv[tid]=cv[tid]; topi[tid]=ci[tid]; }
    } else if(C > 256 && C <= CAP){
        // warp-iterative exact select
        if(tid < 32){
            const int lane = tid;
            for(int it=0; it<KK; ++it){
                float bv = -FLT_MAX; int bi = 0x7fffffff;
                for(int t=lane; t<C; t+=32){
                    float v = cv[t]; int j = ci[t];
                    if(v>bv || (v==bv && j<bi)){ bv=v; bi=j; }
                }
                #pragma unroll
                for(int o=16;o;o>>=1){
                    float ov = __shfl_down_sync(0xffffffffu,bv,o);
                    int   oi = __shfl_down_sync(0xffffffffu,bi,o);
                    if(ov>bv || (ov==bv && oi<bi)){ bv=ov; bi=oi; }
                }
                bv = __shfl_sync(0xffffffffu,bv,0);
                bi = __shfl_sync(0xffffffffu,bi,0);
                if(lane==0){ topv[it]=bv; topi[it]=bi; }
                for(int t=lane; t<C; t+=32) if(ci[t]==bi) cv[t] = -FLT_MAX;
                __syncwarp();
            }
        }
    } else {
        // deterministic full fallback: stage row, 32 iterative block-argmax
        for(int t=tid; t<NN/4; t+=256) ((float4*)srow)[t] = a4[t];
        __syncthreads();
        const int warp = tid>>5, lane = tid&31, base = warp*512;
        for(int it=0; it<KK; ++it){
            float bv=-FLT_MAX; int bi=0x7fffffff;
            #pragma unroll
            for(int t=0;t<16;t++){
                int j = base + t*32 + lane;
                float v = srow[j];
                if(v>bv || (v==bv && j<bi)){ bv=v; bi=j; }
            }
            #pragma unroll
            for(int o=16;o;o>>=1){
                float ov = __shfl_down_sync(0xffffffffu,bv,o);
                int   oi = __shfl_down_sync(0xffffffffu,bi,o);
                if(ov>bv || (ov==bv && oi<bi)){ bv=ov; bi=oi; }
            }
            if(lane==0){ wvs[warp]=bv; wis[warp]=bi; }
            __syncthreads();
            if(tid==0){
                float mv=wvs[0]; int mi=wis[0];
                #pragma unroll
                for(int w=1;w<8;w++)
                    if(wvs[w]>mv || (wvs[w]==mv && wis[w]<mi)){ mv=wvs[w]; mi=wis[w]; }
                topv[it]=mv; topi[it]=mi; srow[mi]=-FLT_MAX;
            }
            __syncthreads();
        }
    }
    __syncthreads();

    if(tid < KK){
        const size_t e = (size_t)row*KK + tid;
        float v = topv[tid];
        int   j = topi[tid];
        g_vals[e] = v;
        g_idx [e] = j;
        int i  = row & (NN-1);
        int vx = (j&63) - (i&63);
        int vy = (j>>6) - (i>>6);
        int off = (vy+63)*NOFF + (vx+63);
        g_off[e] = off;
        atomicAdd(&g_w[(row>>12)*NOFF2 + off], v);
    }
}

// ---------------- K2: Hbins matvec: H[b][o] = dot(w[b], ktT[o]) ---------------
__global__ void k_mat(){
    const int b = blockIdx.x >> 5;
    const int o = blockIdx.x & 31;
    const int tid = threadIdx.x;
    const float* wv = g_w   + (size_t)b*NOFF2;
    const float* kt = g_ktT + (size_t)o*NOFF2;
    float s = 0.f;
    for(int t=tid; t<NOFF2; t+=256) s = fmaf(wv[t], kt[t], s);
    __shared__ float sh[8];
    s = warp_sum(s);
    if((tid&31)==0) sh[tid>>5]=s;
    __syncthreads();
    if(tid<32){
        float v = (tid<8)? sh[tid] : 0.f;
        v = warp_sum(v);
        if(tid==0) g_hbins[blockIdx.x]=v;
    }
}

// ---------------- K4: per-row warp: softmax(H), R, A1, entropy->U, chi --------
__global__ void k_row1(float* __restrict__ outU){
    const int warp = threadIdx.x>>5, lane = threadIdx.x&31;
    const int row  = blockIdx.x*8 + warp;
    const int b    = row >> 12;

    // per-warp recompute of Wsoft/Wmean from g_hbins (64 floats, L2)
    float h0 = g_hbins[lane];
    float h1 = g_hbins[32+lane];
    float x0 = ETA*h0, x1 = ETA*h1;
    float e0 = __expf(x0 - warp_max(x0));
    float e1 = __expf(x1 - warp_max(x1));
    float w0 = __fdividef(e0, warp_sum(e0));
    float w1 = __fdividef(e1, warp_sum(e1));
    const float wl = (b==0) ? w0 : w1;
    const float wm = 0.5f*(w0+w1);

    const size_t e = (size_t)row*KK + lane;
    const int off  = g_off[e];
    const float* krow = g_kt + (size_t)off*32;
    float kv[32];
    #pragma unroll
    for(int t=0;t<8;t++){
        float4 f = ((const float4*)krow)[t];
        kv[4*t+0]=f.x; kv[4*t+1]=f.y; kv[4*t+2]=f.z; kv[4*t+3]=f.w;
    }
    float r = LAMBDA0, chi = 0.f;
    #pragma unroll
    for(int o=0;o<32;o++){
        r   = fmaf(__shfl_sync(0xffffffffu, wl, o), kv[o], r);
        chi = fmaf(__shfl_sync(0xffffffffu, wm, o), kv[o], chi);
    }
    const float val = g_vals[e];
    float ta = val*r;
    float S  = warp_sum(ta);
    float a1 = __fdividef(ta, S+EPS);
    g_a1e[e]=a1;
    g_chi[e]=chi;
    float x  = ALPHA*a1;
    float mx = warp_max(x);
    float ex = __expf(x-mx);
    float se = warp_sum(ex);
    float p  = __fdividef(ex, se);
    float t  = p*__logf(p+EPS);
    float ent= -warp_sum(t);
    float U  = __fdividef(1.f, 1.f+__expf(ent));
    if(lane==0){ outU[row]=U; g_m[row]=1.f-U; }
}

// ---------------- K5: per-row block: A2 edges, dense write, q -----------------
__global__ void k_row2(float* __restrict__ outA2){
    __shared__ float srow[NN];
    __shared__ float sfin[KK];
    __shared__ int   sidx[KK];
    const int row = blockIdx.x;
    const int b   = row >> 12;
    const int tid = threadIdx.x;
    float4 z = make_float4(0.f,0.f,0.f,0.f);
    for(int t=tid; t<NN/4; t+=256) ((float4*)srow)[t]=z;
    if(tid<32){
        const int lane=tid;
        const size_t e = (size_t)row*KK + lane;
        int   j  = g_idx[e];
        float a1 = g_a1e[e];
        float mi = g_m[row];
        float mj = g_m[(b<<12)+j];
        float hat= mi*a1*mj;
        float hs = warp_sum(hat);
        float a2 = __fdividef(hat, hs+EPS);
        float rs = warp_sum(a2);
        float fin= __fdividef(a2, rs+EPS);
        g_a2e[e]=fin;
        sidx[lane]=j; sfin[lane]=fin;
        float x  = BETAP*a2;
        float mx = warp_max(x);
        float ex = __expf(x-mx);
        float se = warp_sum(ex);
        float wlc= __fdividef(ex, se);
        float q  = warp_sum(wlc*g_chi[e]);
        if(lane==0) g_q[row]=q;
    }
    __syncthreads();
    if(tid<32) srow[sidx[tid]] = sfin[tid];
    __syncthreads();
    float4* o4 = (float4*)(outA2 + (size_t)row*NN);
    for(int t=tid; t<NN/4; t+=256) o4[t]=((float4*)srow)[t];
}

// ---------------- K6: directional evidence (1 row per warp) -------------------
__global__ void k_dir(const float* __restrict__ A2){
    const int lane = threadIdx.x & 31;
    const int row  = blockIdx.x*8 + (threadIdx.x>>5);
    const size_t e = (size_t)row*KK + lane;
    int b = row>>12, r = row&(NN-1);
    int c = g_idx[e];
    float val = g_a2e[e];
    float rev = A2[((size_t)(b<<12)+c)*NN + r];
    float pd = 0.f;
    if(r != c){
        float ef = __expf(BETA*val);
        float er = __expf(BETA*rev);
        pd = __fdividef(ef, ef+er+EPS);
    }
    float s = warp_sum(val*pd);
    if(lane==0) g_sev[row]=s;
    atomicAdd(&g_tev[(b<<12)+c], val*(1.f-pd));
}

// ---------------- K7: pi + conv + sigmoid (fused) -----------------------------
__global__ void k_pi_conv(const float* __restrict__ gk,
                          float* __restrict__ outS, float* __restrict__ outT,
                          float* __restrict__ outM){
    int t = blockIdx.x*blockDim.x+threadIdx.x;
    if(t >= BB*NN) return;
    float s=g_sev[t], tt=g_tev[t];
    float ps = __fdividef(s, s+tt+EPS);
    outS[t]=ps; outT[t]=1.f-ps;

    int b = t>>12; int yx = t&(NN-1);
    int y = yx>>6, x = yx&63;
    const float* q = g_q + (b<<12);
    float acc = 0.f;
    #pragma unroll
    for(int dy=0;dy<5;dy++){
        int yy=y+dy-2;
        if(yy<0||yy>=HH) continue;
        #pragma unroll
        for(int dx=0;dx<5;dx++){
            int xx=x+dx-2;
            if(xx<0||xx>=WW) continue;
            acc = fmaf(q[yy*WW+xx], gk[dy*5+dx], acc);
        }
    }
    outM[t] = __fdividef(1.f, 1.f+__expf(-acc));
}

// ---------------- launch ------------------------------------------------------
extern "C" void kernel_launch(void* const* d_in, const int* in_sizes, int n_in,
                              void* d_out, int out_size){
    // inputs: 0=E (unused), 1=A0, 2=P, 3=bins, 4=smooth_kernel
    const float* A0   = (const float*)d_in[1];
    const float* bins = (const float*)d_in[3];
    const float* sker = (const float*)d_in[4];
    float* out = (float*)d_out;

    const size_t OFF_A2  = 0;
    const size_t OFF_U   = (size_t)BB*NN*NN;
    const size_t OFF_PS  = OFF_U  + BB*NN;
    const size_t OFF_PT  = OFF_PS + BB*NN;
    const size_t OFF_MAP = OFF_PT + BB*NN;

    k_table<<<(NOFF2+7)/8, 256>>>(bins);
    k_topk <<<BB*NN, 256>>>(A0);
    k_mat  <<<64, 256>>>();
    k_row1 <<<BB*NN/8, 256>>>(out + OFF_U);
    k_row2 <<<BB*NN, 256>>>(out + OFF_A2);
    k_dir  <<<BB*NN/8, 256>>>(out + OFF_A2);
    k_pi_conv<<<(BB*NN+255)/256, 256>>>(sker, out + OFF_PS, out + OFF_PT, out + OFF_MAP);
}

// round 7
// speedup vs baseline: 3.8758x; 1.2122x over previous
#include <cuda_runtime.h>
#include <math.h>
#include <float.h>
#include <stdint.h>

#define BB   2
#define NN   4096
#define KK   32
#define HH   64
#define WW   64
#define NOFF 127
#define NOFF2 (127*127)

#define EPS      1e-6f
#define LAMBDA0  0.001f
#define TAU2X2   4.5f
#define ETA      8.0f
#define ALPHA    10.0f
#define BETA     8.0f
#define BETAP    8.0f

#define T0   0.98f
#define CAP  512

// ---------------- static device scratch --------------------------------------
__device__ float g_kt  [(size_t)NOFF2*32];     // kappa table [off][bin], 2 MB
__device__ float g_ktT [(size_t)32*NOFF2];     // transposed  [bin][off], 2 MB
__device__ float g_w   [BB*NOFF2];             // per-offset value sums
__device__ float g_hbins[BB*32];
__device__ float g_Rt  [BB*NOFF2];             // R(off) per batch
__device__ float g_chiT[NOFF2];                // chi(off)
__device__ float g_vals[BB*NN*KK];
__device__ int   g_idx [BB*NN*KK];
__device__ int   g_off [BB*NN*KK];
__device__ float g_a1e [BB*NN*KK];
__device__ float g_a2e [BB*NN*KK];
__device__ float g_m   [BB*NN];
__device__ float g_q   [BB*NN];
__device__ float g_sev [BB*NN];
__device__ float g_tev [BB*NN];

__device__ __forceinline__ float warp_sum(float x){
    #pragma unroll
    for(int o=16;o;o>>=1) x += __shfl_xor_sync(0xffffffffu,x,o);
    return x;
}
__device__ __forceinline__ float warp_max(float x){
    #pragma unroll
    for(int o=16;o;o>>=1) x = fmaxf(x,__shfl_xor_sync(0xffffffffu,x,o));
    return x;
}

// ---------------- K0: kappa table + transpose + zero scratch ------------------
__global__ void k_table(const float* __restrict__ bins){
    const int lane = threadIdx.x & 31;
    const int wloc = threadIdx.x >> 5;
    const int off  = blockIdx.x*8 + wloc;
    if(off < NOFF2){
        float vx = (float)(off % NOFF - 63);
        float vy = (float)(off / NOFF - 63);
        float dx = vx - bins[lane*2+0];
        float dy = vy - bins[lane*2+1];
        float kv = __expf(-(dx*dx+dy*dy)/TAU2X2);
        g_kt [(size_t)off*32 + lane] = kv;
        g_ktT[(size_t)lane*NOFF2 + off] = kv;
    }
    int t = blockIdx.x*blockDim.x + threadIdx.x;
    if(t < BB*NN) g_tev[t] = 0.f;
    if(t < BB*NOFF2) g_w[t] = 0.f;
}

// ---------------- K1: top-32 per row (threshold + bitonic) + w-scatter --------
__global__ void k_topk(const float* __restrict__ A0){
    __shared__ float cv[CAP];
    __shared__ int   ci[CAP];
    __shared__ int   cnt;
    __shared__ float topv[KK];
    __shared__ int   topi[KK];
    __shared__ float srow[NN];           // fallback only
    __shared__ float wvs[8];
    __shared__ int   wis[8];

    const int row = blockIdx.x;
    const int tid = threadIdx.x;
    const float4* a4 = (const float4*)(A0 + (size_t)row*NN);
    if(tid==0) cnt = 0;
    __syncthreads();

    #pragma unroll
    for(int k=0;k<4;k++){
        float4 f = __ldcs(&a4[k*256 + tid]);
        float mm = fmaxf(fmaxf(f.x,f.y), fmaxf(f.z,f.w));
        if(mm > T0){
            int jb = (k*256 + tid)*4;
            if(f.x>T0){ int p=atomicAdd(&cnt,1); if(p<CAP){cv[p]=f.x; ci[p]=jb+0;} }
            if(f.y>T0){ int p=atomicAdd(&cnt,1); if(p<CAP){cv[p]=f.y; ci[p]=jb+1;} }
            if(f.z>T0){ int p=atomicAdd(&cnt,1); if(p<CAP){cv[p]=f.z; ci[p]=jb+2;} }
            if(f.w>T0){ int p=atomicAdd(&cnt,1); if(p<CAP){cv[p]=f.w; ci[p]=jb+3;} }
        }
    }
    __syncthreads();
    const int C = cnt;

    if(C >= KK && C <= 128){
        // pad to 128 and bitonic-sort with 128 active threads
        if(tid >= C && tid < 128){ cv[tid] = -FLT_MAX; ci[tid] = 0x7fffffff; }
        __syncthreads();
        #pragma unroll
        for(int k=2;k<=128;k<<=1){
            for(int j=k>>1;j>0;j>>=1){
                int ixj = tid ^ j;
                if(ixj > tid && tid < 128){
                    bool up = ((tid & k) == 0);
                    float va=cv[tid], vb=cv[ixj];
                    int   ia=ci[tid], ib=ci[ixj];
                    bool aFirst = (va>vb) || (va==vb && ia<ib);
                    if(up ? !aFirst : aFirst){
                        cv[tid]=vb; ci[tid]=ib; cv[ixj]=va; ci[ixj]=ia;
                    }
                }
                __syncthreads();
            }
        }
        if(tid<KK){ topv[tid]=cv[tid]; topi[tid]=ci[tid]; }
    } else if(C > 128 && C <= 256){
        if(tid >= C && tid < 256){ cv[tid] = -FLT_MAX; ci[tid] = 0x7fffffff; }
        __syncthreads();
        #pragma unroll
        for(int k=2;k<=256;k<<=1){
            for(int j=k>>1;j>0;j>>=1){
                int ixj = tid ^ j;
                if(ixj > tid && tid < 256){
                    bool up = ((tid & k) == 0);
                    float va=cv[tid], vb=cv[ixj];
                    int   ia=ci[tid], ib=ci[ixj];
                    bool aFirst = (va>vb) || (va==vb && ia<ib);
                    if(up ? !aFirst : aFirst){
                        cv[tid]=vb; ci[tid]=ib; cv[ixj]=va; ci[ixj]=ia;
                    }
                }
                __syncthreads();
            }
        }
        if(tid<KK){ topv[tid]=cv[tid]; topi[tid]=ci[tid]; }
    } else if(C > 256 && C <= CAP){
        // warp-iterative exact select
        if(tid < 32){
            const int lane = tid;
            for(int it=0; it<KK; ++it){
                float bv = -FLT_MAX; int bi = 0x7fffffff;
                for(int t=lane; t<C; t+=32){
                    float v = cv[t]; int j = ci[t];
                    if(v>bv || (v==bv && j<bi)){ bv=v; bi=j; }
                }
                #pragma unroll
                for(int o=16;o;o>>=1){
                    float ov = __shfl_down_sync(0xffffffffu,bv,o);
                    int   oi = __shfl_down_sync(0xffffffffu,bi,o);
                    if(ov>bv || (ov==bv && oi<bi)){ bv=ov; bi=oi; }
                }
                bv = __shfl_sync(0xffffffffu,bv,0);
                bi = __shfl_sync(0xffffffffu,bi,0);
                if(lane==0){ topv[it]=bv; topi[it]=bi; }
                for(int t=lane; t<C; t+=32) if(ci[t]==bi) cv[t] = -FLT_MAX;
                __syncwarp();
            }
        }
    } else {
        // deterministic full fallback: stage row, 32 iterative block-argmax
        for(int t=tid; t<NN/4; t+=256) ((float4*)srow)[t] = a4[t];
        __syncthreads();
        const int warp = tid>>5, lane = tid&31, base = warp*512;
        for(int it=0; it<KK; ++it){
            float bv=-FLT_MAX; int bi=0x7fffffff;
            #pragma unroll
            for(int t=0;t<16;t++){
                int j = base + t*32 + lane;
                float v = srow[j];
                if(v>bv || (v==bv && j<bi)){ bv=v; bi=j; }
            }
            #pragma unroll
            for(int o=16;o;o>>=1){
                float ov = __shfl_down_sync(0xffffffffu,bv,o);
                int   oi = __shfl_down_sync(0xffffffffu,bi,o);
                if(ov>bv || (ov==bv && oi<bi)){ bv=ov; bi=oi; }
            }
            if(lane==0){ wvs[warp]=bv; wis[warp]=bi; }
            __syncthreads();
            if(tid==0){
                float mv=wvs[0]; int mi=wis[0];
                #pragma unroll
                for(int w=1;w<8;w++)
                    if(wvs[w]>mv || (wvs[w]==mv && wis[w]<mi)){ mv=wvs[w]; mi=wis[w]; }
                topv[it]=mv; topi[it]=mi; srow[mi]=-FLT_MAX;
            }
            __syncthreads();
        }
    }
    __syncthreads();

    if(tid < KK){
        const size_t e = (size_t)row*KK + tid;
        float v = topv[tid];
        int   j = topi[tid];
        g_vals[e] = v;
        g_idx [e] = j;
        int i  = row & (NN-1);
        int vx = (j&63) - (i&63);
        int vy = (j>>6) - (i>>6);
        int off = (vy+63)*NOFF + (vx+63);
        g_off[e] = off;
        atomicAdd(&g_w[(row>>12)*NOFF2 + off], v);
    }
}

// ---------------- K2: Hbins matvec: H[b][o] = dot(w[b], ktT[o]) ---------------
__global__ void k_mat(){
    const int b = blockIdx.x >> 5;
    const int o = blockIdx.x & 31;
    const int tid = threadIdx.x;
    const float* wv = g_w   + (size_t)b*NOFF2;
    const float* kt = g_ktT + (size_t)o*NOFF2;
    float s = 0.f;
    for(int t=tid; t<NOFF2; t+=256) s = fmaf(wv[t], kt[t], s);
    __shared__ float sh[8];
    s = warp_sum(s);
    if((tid&31)==0) sh[tid>>5]=s;
    __syncthreads();
    if(tid<32){
        float v = (tid<8)? sh[tid] : 0.f;
        v = warp_sum(v);
        if(tid==0) g_hbins[blockIdx.x]=v;
    }
}

// ---------------- K3: per-offset R & chi tables -------------------------------
__global__ void k_wtab(){
    const int lane = threadIdx.x & 31;
    const int wloc = threadIdx.x >> 5;
    // softmax over hbins (recomputed per warp; trivial)
    float h0 = g_hbins[lane];
    float h1 = g_hbins[32+lane];
    float x0 = ETA*h0, x1 = ETA*h1;
    float e0 = __expf(x0 - warp_max(x0));
    float e1 = __expf(x1 - warp_max(x1));
    float w0 = __fdividef(e0, warp_sum(e0));
    float w1 = __fdividef(e1, warp_sum(e1));
    float wm = 0.5f*(w0+w1);
    const int off = blockIdx.x*8 + wloc;
    if(off < NOFF2){
        float kv = g_kt[(size_t)off*32 + lane];
        float r0 = warp_sum(w0*kv);
        float r1 = warp_sum(w1*kv);
        float cc = warp_sum(wm*kv);
        if(lane==0){
            g_Rt[off]        = LAMBDA0 + r0;
            g_Rt[NOFF2+off]  = LAMBDA0 + r1;
            g_chiT[off]      = cc;
        }
    }
}

// ---------------- K4: per-row warp: A1, entropy->U ----------------------------
__global__ void k_row1(float* __restrict__ outU){
    const int warp = threadIdx.x>>5, lane = threadIdx.x&31;
    const int row  = blockIdx.x*8 + warp;
    const int b    = row >> 12;
    const size_t e = (size_t)row*KK + lane;
    const int off  = g_off[e];
    const float r  = g_Rt[b*NOFF2 + off];
    const float val= g_vals[e];
    float ta = val*r;
    float S  = warp_sum(ta);
    float a1 = __fdividef(ta, S+EPS);
    g_a1e[e]=a1;
    float x  = ALPHA*a1;
    float mx = warp_max(x);
    float ex = __expf(x-mx);
    float se = warp_sum(ex);
    float p  = __fdividef(ex, se);
    float t  = p*__logf(p+EPS);
    float ent= -warp_sum(t);
    float U  = __fdividef(1.f, 1.f+__expf(ent));
    if(lane==0){ outU[row]=U; g_m[row]=1.f-U; }
}

// ---------------- K5: per-row block: A2 edges, dense write, q -----------------
__global__ void k_row2(float* __restrict__ outA2){
    __shared__ float srow[NN];
    __shared__ float sfin[KK];
    __shared__ int   sidx[KK];
    const int row = blockIdx.x;
    const int b   = row >> 12;
    const int tid = threadIdx.x;
    float4 z = make_float4(0.f,0.f,0.f,0.f);
    for(int t=tid; t<NN/4; t+=256) ((float4*)srow)[t]=z;
    if(tid<32){
        const int lane=tid;
        const size_t e = (size_t)row*KK + lane;
        int   j  = g_idx[e];
        float a1 = g_a1e[e];
        float mi = g_m[row];
        float mj = g_m[(b<<12)+j];
        float hat= mi*a1*mj;
        float hs = warp_sum(hat);
        float a2 = __fdividef(hat, hs+EPS);
        float rs = warp_sum(a2);
        float fin= __fdividef(a2, rs+EPS);
        g_a2e[e]=fin;
        sidx[lane]=j; sfin[lane]=fin;
        float x  = BETAP*a2;
        float mx = warp_max(x);
        float ex = __expf(x-mx);
        float se = warp_sum(ex);
        float wlc= __fdividef(ex, se);
        float chi= g_chiT[g_off[e]];
        float q  = warp_sum(wlc*chi);
        if(lane==0) g_q[row]=q;
    }
    __syncthreads();
    if(tid<32) srow[sidx[tid]] = sfin[tid];
    __syncthreads();
    float4* o4 = (float4*)(outA2 + (size_t)row*NN);
    for(int t=tid; t<NN/4; t+=256) o4[t]=((float4*)srow)[t];
}

// ---------------- K6: directional evidence (1 row per warp) -------------------
__global__ void k_dir(const float* __restrict__ A2){
    const int lane = threadIdx.x & 31;
    const int row  = blockIdx.x*8 + (threadIdx.x>>5);
    const size_t e = (size_t)row*KK + lane;
    int b = row>>12, r = row&(NN-1);
    int c = g_idx[e];
    float val = g_a2e[e];
    float rev = __ldcs(&A2[((size_t)(b<<12)+c)*NN + r]);
    float pd = 0.f;
    if(r != c){
        float ef = __expf(BETA*val);
        float er = __expf(BETA*rev);
        pd = __fdividef(ef, ef+er+EPS);
    }
    float s = warp_sum(val*pd);
    if(lane==0) g_sev[row]=s;
    atomicAdd(&g_tev[(b<<12)+c], val*(1.f-pd));
}

// ---------------- K7: pi + conv + sigmoid (fused) -----------------------------
__global__ void k_pi_conv(const float* __restrict__ gk,
                          float* __restrict__ outS, float* __restrict__ outT,
                          float* __restrict__ outM){
    int t = blockIdx.x*blockDim.x+threadIdx.x;
    if(t >= BB*NN) return;
    float s=g_sev[t], tt=g_tev[t];
    float ps = __fdividef(s, s+tt+EPS);
    outS[t]=ps; outT[t]=1.f-ps;

    int b = t>>12; int yx = t&(NN-1);
    int y = yx>>6, x = yx&63;
    const float* q = g_q + (b<<12);
    float acc = 0.f;
    #pragma unroll
    for(int dy=0;dy<5;dy++){
        int yy=y+dy-2;
        if(yy<0||yy>=HH) continue;
        #pragma unroll
        for(int dx=0;dx<5;dx++){
            int xx=x+dx-2;
            if(xx<0||xx>=WW) continue;
            acc = fmaf(q[yy*WW+xx], gk[dy*5+dx], acc);
        }
    }
    outM[t] = __fdividef(1.f, 1.f+__expf(-acc));
}

// ---------------- launch ------------------------------------------------------
extern "C" void kernel_launch(void* const* d_in, const int* in_sizes, int n_in,
                              void* d_out, int out_size){
    // inputs: 0=E (unused), 1=A0, 2=P, 3=bins, 4=smooth_kernel
    const float* A0   = (const float*)d_in[1];
    const float* bins = (const float*)d_in[3];
    const float* sker = (const float*)d_in[4];
    float* out = (float*)d_out;

    const size_t OFF_A2  = 0;
    const size_t OFF_U   = (size_t)BB*NN*NN;
    const size_t OFF_PS  = OFF_U  + BB*NN;
    const size_t OFF_PT  = OFF_PS + BB*NN;
    const size_t OFF_MAP = OFF_PT + BB*NN;

    k_table<<<(NOFF2+7)/8, 256>>>(bins);
    k_topk <<<BB*NN, 256>>>(A0);
    k_mat  <<<64, 256>>>();
    k_wtab <<<(NOFF2+7)/8, 256>>>();
    k_row1 <<<BB*NN/8, 256>>>(out + OFF_U);
    k_row2 <<<BB*NN, 256>>>(out + OFF_A2);
    k_dir  <<<BB*NN/8, 256>>>(out + OFF_A2);
    k_pi_conv<<<(BB*NN+255)/256, 256>>>(sker, out + OFF_PS, out + OFF_PT, out + OFF_MAP);
}